// round 2
// baseline (speedup 1.0000x reference)
#include <cuda_runtime.h>

// LSTM: B=1024, T=2048, H=32, I=1.
// 2 warps per batch element (64-thread CTA). Warp w owns k-columns [16w,16w+16)
// of the recurrent GEMV. Lane j owns hidden unit j. Gates packed (i,f),(g,o)
// in f32x2. Warp1 writes partial sums to smem; warp0 combines, activates,
// updates (c,h), broadcasts h via duplicated smem pairs.

#define B_ 1024
#define T_ 2048
#define H_ 32

static __device__ __forceinline__ unsigned long long pk2(float lo, float hi) {
    unsigned long long r;
    asm("mov.b64 %0, {%1, %2};" : "=l"(r) : "f"(lo), "f"(hi));
    return r;
}
static __device__ __forceinline__ void upk2(unsigned long long v, float& lo, float& hi) {
    asm("mov.b64 {%0, %1}, %2;" : "=f"(lo), "=f"(hi) : "l"(v));
}
static __device__ __forceinline__ unsigned long long fma2(unsigned long long a,
                                                          unsigned long long b,
                                                          unsigned long long c) {
    unsigned long long d;
    asm("fma.rn.f32x2 %0, %1, %2, %3;" : "=l"(d) : "l"(a), "l"(b), "l"(c));
    return d;
}
static __device__ __forceinline__ unsigned long long add2(unsigned long long a,
                                                          unsigned long long b) {
    unsigned long long d;
    asm("add.rn.f32x2 %0, %1, %2;" : "=l"(d) : "l"(a), "l"(b));
    return d;
}
static __device__ __forceinline__ float ex2f(float x) {
    float r; asm("ex2.approx.f32 %0, %1;" : "=f"(r) : "f"(x)); return r;
}
static __device__ __forceinline__ float rcpf(float x) {
    float r; asm("rcp.approx.f32 %0, %1;" : "=f"(r) : "f"(x)); return r;
}

__global__ void __launch_bounds__(64)
lstm_kernel(const float* __restrict__ x,
            const float* __restrict__ W_ih,
            const float* __restrict__ W_hh,
            const float* __restrict__ b_ih,
            const float* __restrict__ b_hh,
            const float* __restrict__ W_out,
            const float* __restrict__ b_out,
            float* __restrict__ out) {
    const int lane = threadIdx.x & 31;   // hidden unit j
    const int w    = threadIdx.x >> 5;   // warp id within pair (0 or 1)
    const int b    = blockIdx.x;         // batch element
    const int j    = lane;
    const int k0   = w * 16;             // my k-column range start

    __shared__ unsigned long long hb[H_];        // duplicated (h,h) pairs
    __shared__ unsigned long long part[2][H_];   // warp1 partials: [aif|ago][lane]
    __shared__ float pbuf[32][33];               // per-step output partials (warp0 only)

    const float L = 1.4426950408889634f;         // log2(e)
    const float sI = -L, sF = -L, sG = -2.0f * L, sO = -L;

    // Pre-scaled packed recurrent weights for my 16 k-columns.
    unsigned long long wif[16], wgo[16];
#pragma unroll
    for (int kk = 0; kk < 16; kk++) {
        const int k = k0 + kk;
        wif[kk] = pk2(sI * W_hh[(0 * H_ + j) * H_ + k],
                      sF * W_hh[(1 * H_ + j) * H_ + k]);
        wgo[kk] = pk2(sG * W_hh[(2 * H_ + j) * H_ + k],
                      sO * W_hh[(3 * H_ + j) * H_ + k]);
    }

    // Warp0-only constants (input weights, biases, output weights).
    unsigned long long wih_if = 0, wih_go = 0, bs_if = 0, bs_go = 0;
    float wout = 0.0f, bout = 0.0f;
    if (w == 0) {
        wih_if = pk2(sI * W_ih[0 * H_ + j], sF * W_ih[1 * H_ + j]);
        wih_go = pk2(sG * W_ih[2 * H_ + j], sO * W_ih[3 * H_ + j]);
        bs_if  = pk2(sI * (b_ih[0 * H_ + j] + b_hh[0 * H_ + j]),
                     sF * (b_ih[1 * H_ + j] + b_hh[1 * H_ + j]));
        bs_go  = pk2(sG * (b_ih[2 * H_ + j] + b_hh[2 * H_ + j]),
                     sO * (b_ih[3 * H_ + j] + b_hh[3 * H_ + j]));
        wout = W_out[j];
        bout = b_out[0];
        hb[lane] = 0ull;  // h_{-1} = 0
    }
    float c = 0.0f;
    __syncthreads();

    const float* xb = x + (size_t)b * T_;
    float* ob = out + (size_t)b * T_;
    float xc = (w == 0) ? xb[0] : 0.0f;

    for (int t0 = 0; t0 < T_; t0 += 32) {
#pragma unroll 2
        for (int tt = 0; tt < 32; ++tt) {
            const int t = t0 + tt;

            // ---- FMA phase (both warps, own k-half) ----
            unsigned long long a0, g0;
            unsigned long long a1 = 0ull, g1 = 0ull;
            float xn = 0.0f;
            if (w == 0) {
                const int tn = (t + 1 < T_) ? (t + 1) : (T_ - 1);
                xn = xb[tn];  // prefetch next x (L1-resident broadcast)
                const unsigned long long xd = pk2(xc, xc);
                a0 = fma2(xd, wih_if, bs_if);
                g0 = fma2(xd, wih_go, bs_go);
            } else {
                a0 = 0ull; g0 = 0ull;
            }
#pragma unroll
            for (int kk = 0; kk < 16; kk += 2) {
                const unsigned long long h0 = hb[k0 + kk];
                const unsigned long long h1 = hb[k0 + kk + 1];
                a0 = fma2(h0, wif[kk],     a0);
                g0 = fma2(h0, wgo[kk],     g0);
                a1 = fma2(h1, wif[kk + 1], a1);
                g1 = fma2(h1, wgo[kk + 1], g1);
            }
            unsigned long long aif = add2(a0, a1);
            unsigned long long ago = add2(g0, g1);

            if (w == 1) {
                part[0][lane] = aif;
                part[1][lane] = ago;
            }
            __syncthreads();  // bar A: warp1 partials visible

            if (w == 0) {
                aif = add2(aif, part[0][lane]);
                ago = add2(ago, part[1][lane]);

                float ai, af, ag, ao;
                upk2(aif, ai, af);
                upk2(ago, ag, ao);

                // sigmoid(a) = rcp(1 + ex2(-L*a)); preacts already pre-scaled.
                const float i_ = rcpf(1.0f + ex2f(ai));
                const float f_ = rcpf(1.0f + ex2f(af));
                // tanh(a) = 2*rcp(1 + ex2(-2L*a)) - 1
                const float g_ = fmaf(rcpf(1.0f + ex2f(ag)), 2.0f, -1.0f);
                const float o_ = rcpf(1.0f + ex2f(ao));

                c = fmaf(f_, c, i_ * g_);
                const float tc = fmaf(rcpf(1.0f + ex2f(c * sG)), 2.0f, -1.0f);
                const float h = o_ * tc;

                hb[lane] = pk2(h, h);
                pbuf[tt][lane] = h * wout;
                xc = xn;
            }
            __syncthreads();  // bar B: new h visible
        }
        // Transposed output reduction (warp0): lane j sums timestep t0+j.
        if (w == 0) {
            float s0 = 0.0f, s1 = 0.0f;
#pragma unroll
            for (int k = 0; k < 32; k += 2) {
                s0 += pbuf[lane][k];
                s1 += pbuf[lane][k + 1];
            }
            ob[t0 + lane] = s0 + s1 + bout;
        }
        // pbuf is warp0-private; program order within warp0 protects reuse.
    }
}

extern "C" void kernel_launch(void* const* d_in, const int* in_sizes, int n_in,
                              void* d_out, int out_size) {
    const float* x     = (const float*)d_in[0];
    const float* W_ih  = (const float*)d_in[1];
    const float* W_hh  = (const float*)d_in[2];
    const float* b_ih  = (const float*)d_in[3];
    const float* b_hh  = (const float*)d_in[4];
    const float* W_out = (const float*)d_in[5];
    const float* b_out = (const float*)d_in[6];
    float* out = (float*)d_out;

    lstm_kernel<<<B_, 64>>>(x, W_ih, W_hh, b_ih, b_hh, W_out, b_out, out);
}

// round 3
// speedup vs baseline: 1.6970x; 1.6970x over previous
#include <cuda_runtime.h>

// LSTM: B=1024, T=2048, H=32, I=1.
// One warp per batch element (R1 structure). Lane j owns hidden unit j.
// Gates packed (i,f),(g,o) in f32x2; h broadcast via duplicated smem pairs.
// Activations via MUFU.TANH: sigmoid(a)=0.5*tanh(a/2)+0.5 (weights pre-scaled).

#define B_ 1024
#define T_ 2048
#define H_ 32

static __device__ __forceinline__ unsigned long long pk2(float lo, float hi) {
    unsigned long long r;
    asm("mov.b64 %0, {%1, %2};" : "=l"(r) : "f"(lo), "f"(hi));
    return r;
}
static __device__ __forceinline__ void upk2(unsigned long long v, float& lo, float& hi) {
    asm("mov.b64 {%0, %1}, %2;" : "=f"(lo), "=f"(hi) : "l"(v));
}
static __device__ __forceinline__ unsigned long long fma2(unsigned long long a,
                                                          unsigned long long b,
                                                          unsigned long long c) {
    unsigned long long d;
    asm("fma.rn.f32x2 %0, %1, %2, %3;" : "=l"(d) : "l"(a), "l"(b), "l"(c));
    return d;
}
static __device__ __forceinline__ unsigned long long add2(unsigned long long a,
                                                          unsigned long long b) {
    unsigned long long d;
    asm("add.rn.f32x2 %0, %1, %2;" : "=l"(d) : "l"(a), "l"(b));
    return d;
}
static __device__ __forceinline__ float tanhf_(float x) {
    float r; asm("tanh.approx.f32 %0, %1;" : "=f"(r) : "f"(x)); return r;
}

__global__ void __launch_bounds__(32)
lstm_kernel(const float* __restrict__ x,
            const float* __restrict__ W_ih,
            const float* __restrict__ W_hh,
            const float* __restrict__ b_ih,
            const float* __restrict__ b_hh,
            const float* __restrict__ W_out,
            const float* __restrict__ b_out,
            float* __restrict__ out) {
    const int j = threadIdx.x;   // hidden unit
    const int b = blockIdx.x;    // batch element

    __shared__ unsigned long long hb[2][H_];  // duplicated (h,h) pairs, double-buffered
    __shared__ float pbuf[32][33];            // per-step output partials (padded)

    // Pre-scales: sigmoid gates get 0.5 (sigmoid(a)=0.5*tanh(a/2)+0.5),
    // tanh gate g gets 1.0.
    const float sI = 0.5f, sF = 0.5f, sG = 1.0f, sO = 0.5f;

    unsigned long long wif[H_], wgo[H_];
#pragma unroll
    for (int k = 0; k < H_; k++) {
        wif[k] = pk2(sI * W_hh[(0 * H_ + j) * H_ + k],
                     sF * W_hh[(1 * H_ + j) * H_ + k]);
        wgo[k] = pk2(sG * W_hh[(2 * H_ + j) * H_ + k],
                     sO * W_hh[(3 * H_ + j) * H_ + k]);
    }
    const unsigned long long wih_if = pk2(sI * W_ih[0 * H_ + j], sF * W_ih[1 * H_ + j]);
    const unsigned long long wih_go = pk2(sG * W_ih[2 * H_ + j], sO * W_ih[3 * H_ + j]);
    const unsigned long long bs_if  = pk2(sI * (b_ih[0 * H_ + j] + b_hh[0 * H_ + j]),
                                          sF * (b_ih[1 * H_ + j] + b_hh[1 * H_ + j]));
    const unsigned long long bs_go  = pk2(sG * (b_ih[2 * H_ + j] + b_hh[2 * H_ + j]),
                                          sO * (b_ih[3 * H_ + j] + b_hh[3 * H_ + j]));
    const float wout = W_out[j];
    const float bout = b_out[0];
    const unsigned long long z2 = 0ull;

    float c = 0.0f;
    hb[0][j] = 0ull;   // h_{-1} = 0
    __syncwarp();

    const float* xb = x + (size_t)b * T_;
    float* ob = out + (size_t)b * T_;
    float xc = xb[0];

    for (int t0 = 0; t0 < T_; t0 += 32) {
#pragma unroll 2
        for (int tt = 0; tt < 32; ++tt) {
            const int t = t0 + tt;
            const int tn = (t + 1 < T_) ? (t + 1) : (T_ - 1);
            const float xn = xb[tn];   // prefetch next x (L1-resident broadcast)

            const unsigned long long xd = pk2(xc, xc);
            unsigned long long a0 = fma2(xd, wih_if, bs_if);  // (i/2, f/2)
            unsigned long long a1 = z2;
            unsigned long long g0 = fma2(xd, wih_go, bs_go);  // (g, o/2)
            unsigned long long g1 = z2;

            const unsigned long long* hp = hb[t & 1];
#pragma unroll
            for (int k = 0; k < H_; k += 2) {
                const unsigned long long h0 = hp[k];
                const unsigned long long h1 = hp[k + 1];
                a0 = fma2(h0, wif[k],     a0);
                g0 = fma2(h0, wgo[k],     g0);
                a1 = fma2(h1, wif[k + 1], a1);
                g1 = fma2(h1, wgo[k + 1], g1);
            }
            const unsigned long long aif = add2(a0, a1);
            const unsigned long long ago = add2(g0, g1);

            float ai, af, ag, ao;
            upk2(aif, ai, af);
            upk2(ago, ag, ao);

            // sigmoid via tanh: preacts already halved for i,f,o.
            const float i_ = fmaf(tanhf_(ai), 0.5f, 0.5f);
            const float f_ = fmaf(tanhf_(af), 0.5f, 0.5f);
            const float g_ = tanhf_(ag);
            const float o_ = fmaf(tanhf_(ao), 0.5f, 0.5f);

            c = fmaf(f_, c, i_ * g_);
            const float h = o_ * tanhf_(c);

            hb[(t + 1) & 1][j] = pk2(h, h);
            pbuf[tt][j] = h * wout;
            __syncwarp();
            xc = xn;
        }
        // Transposed reduction: lane j sums the 32 partials of timestep t0+j.
        float s0 = 0.0f, s1 = 0.0f;
#pragma unroll
        for (int k = 0; k < 32; k += 2) {
            s0 += pbuf[j][k];
            s1 += pbuf[j][k + 1];
        }
        ob[t0 + j] = s0 + s1 + bout;
        __syncwarp();  // protect pbuf before next block overwrites it
    }
}

extern "C" void kernel_launch(void* const* d_in, const int* in_sizes, int n_in,
                              void* d_out, int out_size) {
    const float* x     = (const float*)d_in[0];
    const float* W_ih  = (const float*)d_in[1];
    const float* W_hh  = (const float*)d_in[2];
    const float* b_ih  = (const float*)d_in[3];
    const float* b_hh  = (const float*)d_in[4];
    const float* W_out = (const float*)d_in[5];
    const float* b_out = (const float*)d_in[6];
    float* out = (float*)d_out;

    lstm_kernel<<<B_, 32>>>(x, W_ih, W_hh, b_ih, b_hh, W_out, b_out, out);
}

// round 4
// speedup vs baseline: 1.8010x; 1.0613x over previous
#include <cuda_runtime.h>

// LSTM: B=1024, T=2048, H=32, I=1.
// One warp per batch element. Lane j owns hidden unit j.
// Gates packed (i,f),(g,o) in f32x2; h broadcast via duplicated smem pairs
// (double-buffered, warp-converged -> no __syncwarp needed).
// Activations via MUFU.TANH; sigmoid(a)=0.5*tanh(a/2)+0.5 (weights pre-scaled).

#define B_ 1024
#define T_ 2048
#define H_ 32

typedef unsigned long long u64;

static __device__ __forceinline__ u64 pk2(float lo, float hi) {
    u64 r;
    asm("mov.b64 %0, {%1, %2};" : "=l"(r) : "f"(lo), "f"(hi));
    return r;
}
static __device__ __forceinline__ void upk2(u64 v, float& lo, float& hi) {
    asm("mov.b64 {%0, %1}, %2;" : "=f"(lo), "=f"(hi) : "l"(v));
}
static __device__ __forceinline__ u64 fma2(u64 a, u64 b, u64 c) {
    u64 d;
    asm("fma.rn.f32x2 %0, %1, %2, %3;" : "=l"(d) : "l"(a), "l"(b), "l"(c));
    return d;
}
static __device__ __forceinline__ u64 add2(u64 a, u64 b) {
    u64 d;
    asm("add.rn.f32x2 %0, %1, %2;" : "=l"(d) : "l"(a), "l"(b));
    return d;
}
static __device__ __forceinline__ float tanhf_(float x) {
    float r; asm("tanh.approx.f32 %0, %1;" : "=f"(r) : "f"(x)); return r;
}
static __device__ __forceinline__ void lds2(u64& p0, u64& p1, unsigned addr) {
    asm volatile("ld.shared.v2.b64 {%0, %1}, [%2];"
                 : "=l"(p0), "=l"(p1) : "r"(addr));
}
static __device__ __forceinline__ void sts64(unsigned addr, u64 v) {
    asm volatile("st.shared.b64 [%0], %1;" :: "r"(addr), "l"(v));
}

__global__ void __launch_bounds__(32)
lstm_kernel(const float* __restrict__ x,
            const float* __restrict__ W_ih,
            const float* __restrict__ W_hh,
            const float* __restrict__ b_ih,
            const float* __restrict__ b_hh,
            const float* __restrict__ W_out,
            const float* __restrict__ b_out,
            float* __restrict__ out) {
    const int j = threadIdx.x;   // hidden unit
    const int b = blockIdx.x;    // batch element

    __shared__ u64 hbuf[2][H_];               // duplicated (h,h) pairs, double-buffered
    __shared__ float pbuf[32][33];            // per-step output partials (padded)
    volatile float (*pv)[33] = (volatile float (*)[33])pbuf;

    const float sI = 0.5f, sF = 0.5f, sG = 1.0f, sO = 0.5f;

    // Pre-scaled packed recurrent weights.
    u64 wif[H_], wgo[H_];
#pragma unroll
    for (int k = 0; k < H_; k++) {
        wif[k] = pk2(sI * W_hh[(0 * H_ + j) * H_ + k],
                     sF * W_hh[(1 * H_ + j) * H_ + k]);
        wgo[k] = pk2(sG * W_hh[(2 * H_ + j) * H_ + k],
                     sO * W_hh[(3 * H_ + j) * H_ + k]);
    }
    const u64 wih_if = pk2(sI * W_ih[0 * H_ + j], sF * W_ih[1 * H_ + j]);
    const u64 wih_go = pk2(sG * W_ih[2 * H_ + j], sO * W_ih[3 * H_ + j]);
    const u64 bs_if  = pk2(sI * (b_ih[0 * H_ + j] + b_hh[0 * H_ + j]),
                           sF * (b_ih[1 * H_ + j] + b_hh[1 * H_ + j]));
    const u64 bs_go  = pk2(sG * (b_ih[2 * H_ + j] + b_hh[2 * H_ + j]),
                           sO * (b_ih[3 * H_ + j] + b_hh[3 * H_ + j]));
    const float wout = W_out[j];
    const float bout = b_out[0];
    const u64 z2 = 0ull;

    const unsigned hb0 = (unsigned)__cvta_generic_to_shared(&hbuf[0][0]);
    const unsigned hb1 = hb0 + (unsigned)(H_ * sizeof(u64));
    const unsigned st0 = hb0 + j * 8;
    const unsigned st1 = hb1 + j * 8;

    float c = 0.0f;
    sts64(st0, z2);    // h_{-1} = 0 (warp-converged: visible to later LDS in-order)

    const float* xb = x + (size_t)b * T_;
    float* ob = out + (size_t)b * T_;
    float xc = xb[0];

    for (int t0 = 0; t0 < T_; t0 += 32) {
#pragma unroll 2
        for (int tt = 0; tt < 32; ++tt) {
            const int t = t0 + tt;
            const int tn = (t + 1 < T_) ? (t + 1) : (T_ - 1);
            const float xn = xb[tn];   // prefetch next x (L1-resident broadcast)

            const unsigned rdaddr = (t & 1) ? hb1 : hb0;
            const unsigned wraddr = (t & 1) ? st0 : st1;

            const u64 xd = pk2(xc, xc);

            // ---- Phase 1: (i,f) chains over all 32 h; stash h pairs ----
            u64 hr[H_];
            u64 a0 = fma2(xd, wih_if, bs_if);
            u64 a1 = z2;
#pragma unroll
            for (int k = 0; k < H_; k += 2) {
                u64 p0, p1;
                lds2(p0, p1, rdaddr + k * 8);
                hr[k] = p0;
                hr[k + 1] = p1;
                a0 = fma2(p0, wif[k],     a0);
                a1 = fma2(p1, wif[k + 1], a1);
            }
            const u64 aif = add2(a0, a1);
            float ai, af;
            upk2(aif, ai, af);
            const float ti = tanhf_(ai);   // MUFU overlaps phase-2 FMA issue
            const float tf = tanhf_(af);

            // ---- Phase 2: (g,o) chains from stashed h ----
            u64 g0 = fma2(xd, wih_go, bs_go);
            u64 g1 = z2;
#pragma unroll
            for (int k = 0; k < H_; k += 2) {
                g0 = fma2(hr[k],     wgo[k],     g0);
                g1 = fma2(hr[k + 1], wgo[k + 1], g1);
            }
            const u64 ago = add2(g0, g1);
            float ag, ao;
            upk2(ago, ag, ao);
            const float g_ = tanhf_(ag);
            const float to = tanhf_(ao);

            const float i_ = fmaf(ti, 0.5f, 0.5f);
            const float f_ = fmaf(tf, 0.5f, 0.5f);
            const float o_ = fmaf(to, 0.5f, 0.5f);

            c = fmaf(f_, c, i_ * g_);
            const float h = o_ * tanhf_(c);

            sts64(wraddr, pk2(h, h));      // broadcast h (no sync: converged warp)
            pv[tt][j] = h * wout;
            xc = xn;
        }
        // Transposed reduction: lane j sums the 32 partials of timestep t0+j.
        float s0 = 0.0f, s1 = 0.0f;
#pragma unroll
        for (int k = 0; k < 32; k += 2) {
            s0 += pv[j][k];
            s1 += pv[j][k + 1];
        }
        ob[t0 + j] = s0 + s1 + bout;
    }
}

extern "C" void kernel_launch(void* const* d_in, const int* in_sizes, int n_in,
                              void* d_out, int out_size) {
    const float* x     = (const float*)d_in[0];
    const float* W_ih  = (const float*)d_in[1];
    const float* W_hh  = (const float*)d_in[2];
    const float* b_ih  = (const float*)d_in[3];
    const float* b_hh  = (const float*)d_in[4];
    const float* W_out = (const float*)d_in[5];
    const float* b_out = (const float*)d_in[6];
    float* out = (float*)d_out;

    lstm_kernel<<<B_, 32>>>(x, W_ih, W_hh, b_ih, b_hh, W_out, b_out, out);
}